// round 2
// baseline (speedup 1.0000x reference)
#include <cuda_runtime.h>
#include <cuda_bf16.h>

#define NN 30000
#define MM 16
#define KK 8
#define DDIM 32
#define DREP 256
#define NFEAT 1024
#define NCLASS 16

// Scratch (device globals: allowed, no runtime allocation)
__device__ float g_h[NN * DREP];              // layer activations
__device__ float g_xn[(NN + 1) * DREP];       // normalized table + zero pad row

// ---------------------------------------------------------------------------
// PCA GEMM: C = relu(A[NN,1024] @ B[1024,256] + bias), fp32 register-blocked
// BM=128, BN=64, BK=16, 256 threads, 8x4 micro-tile
// ---------------------------------------------------------------------------
#define BM 128
#define BN 64
#define BK 16

__global__ __launch_bounds__(256) void pca_gemm_kernel(
    const float* __restrict__ A, const float* __restrict__ B,
    const float* __restrict__ bias, float* __restrict__ C)
{
    __shared__ float As[BK][132];   // transposed, padded stride
    __shared__ float Bs[BK][BN];

    int tid = threadIdx.x;
    int rowBase = blockIdx.x * BM;
    int colBase = blockIdx.y * BN;
    int ty = tid >> 4;      // 0..15 -> rows ty*8 .. ty*8+7
    int tx = tid & 15;      // 0..15 -> cols tx*4 .. tx*4+3

    float acc[8][4];
#pragma unroll
    for (int i = 0; i < 8; i++)
#pragma unroll
        for (int j = 0; j < 4; j++) acc[i][j] = 0.f;

    for (int k0 = 0; k0 < NFEAT; k0 += BK) {
        // Load A tile (128x16): 512 float4, 2 per thread, store transposed
#pragma unroll
        for (int l = 0; l < 2; l++) {
            int idx = tid + l * 256;
            int r = idx >> 2;
            int c4 = (idx & 3) << 2;
            int row = rowBase + r;
            float4 v = make_float4(0.f, 0.f, 0.f, 0.f);
            if (row < NN)
                v = *(const float4*)(A + (size_t)row * NFEAT + k0 + c4);
            As[c4 + 0][r] = v.x;
            As[c4 + 1][r] = v.y;
            As[c4 + 2][r] = v.z;
            As[c4 + 3][r] = v.w;
        }
        // Load B tile (16x64): 256 float4, 1 per thread
        {
            int r = tid >> 4;
            int c4 = (tid & 15) << 2;
            float4 v = *(const float4*)(B + (size_t)(k0 + r) * DREP + colBase + c4);
            *(float4*)(&Bs[r][c4]) = v;
        }
        __syncthreads();

#pragma unroll
        for (int kk = 0; kk < BK; kk++) {
            float4 a0 = *(const float4*)(&As[kk][ty * 8]);
            float4 a1 = *(const float4*)(&As[kk][ty * 8 + 4]);
            float4 bv = *(const float4*)(&Bs[kk][tx * 4]);
            float a[8] = {a0.x, a0.y, a0.z, a0.w, a1.x, a1.y, a1.z, a1.w};
            float b[4] = {bv.x, bv.y, bv.z, bv.w};
#pragma unroll
            for (int i = 0; i < 8; i++)
#pragma unroll
                for (int j = 0; j < 4; j++)
                    acc[i][j] = fmaf(a[i], b[j], acc[i][j]);
        }
        __syncthreads();
    }

#pragma unroll
    for (int i = 0; i < 8; i++) {
        int row = rowBase + ty * 8 + i;
        if (row < NN) {
#pragma unroll
            for (int j = 0; j < 4; j++) {
                int col = colBase + tx * 4 + j;
                C[(size_t)row * DREP + col] = fmaxf(acc[i][j] + bias[col], 0.f);
            }
        }
    }
}

// ---------------------------------------------------------------------------
// Prep layer 0: per-capsule l2norm -> fc (32x32 per capsule) + relu -> l2norm
// One block per node (plus pad block NN), 256 threads: (k = t>>5, o = t&31)
// ---------------------------------------------------------------------------
__global__ __launch_bounds__(256) void prep0_kernel(
    const float* __restrict__ fc_w, const float* __restrict__ fc_b)
{
    int n = blockIdx.x;
    int t = threadIdx.x;
    int k = t >> 5;
    int o = t & 31;
    if (n == NN) { g_xn[(size_t)NN * DREP + t] = 0.f; return; }

    __shared__ float sx[DREP];
    float xv = g_h[(size_t)n * DREP + t];
    float ss = xv * xv;
#pragma unroll
    for (int off = 16; off >= 1; off >>= 1)
        ss += __shfl_xor_sync(0xffffffffu, ss, off);
    float xn = xv / fmaxf(sqrtf(ss), 1e-12f);
    sx[t] = xn;
    __syncthreads();

    float y = fc_b[k * DDIM + o];
    const float* w = fc_w + (size_t)(k * DDIM + o) * DDIM;
    const float* xk = &sx[k * DDIM];
#pragma unroll
    for (int i = 0; i < DDIM; i++)
        y = fmaf(xk[i], w[i], y);
    y = fmaxf(y, 0.f);

    float ss2 = y * y;
#pragma unroll
    for (int off = 16; off >= 1; off >>= 1)
        ss2 += __shfl_xor_sync(0xffffffffu, ss2, off);
    g_xn[(size_t)n * DREP + t] = y / fmaxf(sqrtf(ss2), 1e-12f);
}

// ---------------------------------------------------------------------------
// Prep layers 1/2: per-capsule l2norm only
// ---------------------------------------------------------------------------
__global__ __launch_bounds__(256) void prep_norm_kernel()
{
    int n = blockIdx.x;
    int t = threadIdx.x;
    if (n == NN) { g_xn[(size_t)NN * DREP + t] = 0.f; return; }
    float xv = g_h[(size_t)n * DREP + t];
    float ss = xv * xv;
#pragma unroll
    for (int off = 16; off >= 1; off >>= 1)
        ss += __shfl_xor_sync(0xffffffffu, ss, off);
    g_xn[(size_t)n * DREP + t] = xv / fmaxf(sqrtf(ss), 1e-12f);
}

// ---------------------------------------------------------------------------
// Routing: one block per node, 256 threads: (k = warp = t>>5, dd = lane)
// z[m] kept in registers (16 per thread). 6 dynamic-routing iterations.
// ---------------------------------------------------------------------------
__global__ __launch_bounds__(256) void routing_kernel(
    const int* __restrict__ nbrs, const float* __restrict__ raw_param,
    const int* __restrict__ routit_p, float* __restrict__ out_h, int do_relu)
{
    int n = blockIdx.x;
    int t = threadIdx.x;
    int k = t >> 5;
    int dd = t & 31;

    __shared__ int snbr[MM];
    __shared__ float se[MM * KK];
    __shared__ float s2arr[MM];

    if (t < MM) snbr[t] = nbrs[(size_t)n * MM + t];
    __syncthreads();

    float z[MM];
#pragma unroll
    for (int m = 0; m < MM; m++) {
        int nb = snbr[m];
        z[m] = g_xn[(size_t)nb * DREP + t];
    }
    float u_acc = g_xn[(size_t)n * DREP + t];   // u_before init (normalized x)
    float u_n = u_acc;

    float param = 1.f / (1.f + __expf(-raw_param[0]));
    float q = 1.f - param;
    int nit = *routit_p;

    float p[MM];
    for (int it = 0; it < nit; it++) {
        if (it == 0) {
#pragma unroll
            for (int m = 0; m < MM; m++) p[m] = 0.f;
        } else {
#pragma unroll
            for (int m = 0; m < MM; m++) p[m] = z[m] * u_n;
#pragma unroll
            for (int off = 16; off >= 1; off >>= 1) {
#pragma unroll
                for (int m = 0; m < MM; m++)
                    p[m] += __shfl_xor_sync(0xffffffffu, p[m], off);
            }
        }
        // exp (|p| <= 1, no max-shift needed) and neighbor-softmax denom
        float s1 = 0.f;
#pragma unroll
        for (int m = 0; m < MM; m++) {
            p[m] = __expf(p[m]);
            s1 += p[m];
        }
        // capsule-softmax denominators via shared memory
        if (dd < MM) se[dd * KK + k] = p[dd];
        __syncthreads();
        if (t < MM) {
            float s = 0.f;
#pragma unroll
            for (int kk = 0; kk < KK; kk++) s += se[t * KK + kk];
            s2arr[t] = s;
        }
        __syncthreads();

        float inv_s1 = param / s1;
#pragma unroll
        for (int m = 0; m < MM; m++) {
            float w = p[m] * inv_s1 + q * p[m] / s2arr[m];
            u_acc = fmaf(z[m], w, u_acc);
        }
        if (it < nit - 1) {
            float ss = u_acc * u_acc;
#pragma unroll
            for (int off = 16; off >= 1; off >>= 1)
                ss += __shfl_xor_sync(0xffffffffu, ss, off);
            u_n = u_acc / fmaxf(sqrtf(ss), 1e-12f);
        }
        __syncthreads();   // protect se/s2arr reuse
    }

    float v = u_acc;
    if (do_relu) v = fmaxf(v, 0.f);
    out_h[(size_t)n * DREP + t] = v;
}

// ---------------------------------------------------------------------------
// Final MLP + log_softmax. One warp per node.
// ---------------------------------------------------------------------------
__global__ __launch_bounds__(256) void mlp_kernel(
    const float* __restrict__ h, const float* __restrict__ mlp_w,
    const float* __restrict__ mlp_b, float* __restrict__ out)
{
    int gwarp = (blockIdx.x * blockDim.x + threadIdx.x) >> 5;
    int lane = threadIdx.x & 31;
    if (gwarp >= NN) return;

    float acc[NCLASS];
#pragma unroll
    for (int c = 0; c < NCLASS; c++) acc[c] = 0.f;

#pragma unroll
    for (int j = 0; j < DREP / 32; j++) {
        float hv = h[(size_t)gwarp * DREP + j * 32 + lane];
#pragma unroll
        for (int c = 0; c < NCLASS; c++)
            acc[c] = fmaf(hv, mlp_w[(size_t)c * DREP + j * 32 + lane], acc[c]);
    }
#pragma unroll
    for (int off = 16; off >= 1; off >>= 1) {
#pragma unroll
        for (int c = 0; c < NCLASS; c++)
            acc[c] += __shfl_xor_sync(0xffffffffu, acc[c], off);
    }
    if (lane == 0) {
        float mx = -1e30f;
#pragma unroll
        for (int c = 0; c < NCLASS; c++) {
            acc[c] += mlp_b[c];
            mx = fmaxf(mx, acc[c]);
        }
        float s = 0.f;
#pragma unroll
        for (int c = 0; c < NCLASS; c++) s += expf(acc[c] - mx);
        float ls = logf(s);
#pragma unroll
        for (int c = 0; c < NCLASS; c++)
            out[(size_t)gwarp * NCLASS + c] = acc[c] - mx - ls;
    }
}

// ---------------------------------------------------------------------------
// Launch
// ---------------------------------------------------------------------------
extern "C" void kernel_launch(void* const* d_in, const int* in_sizes, int n_in,
                              void* d_out, int out_size)
{
    const float* x        = (const float*)d_in[0];
    const int*   nbrs     = (const int*)d_in[1];
    const float* pca_w    = (const float*)d_in[2];
    const float* pca_b    = (const float*)d_in[3];
    const float* rawp     = (const float*)d_in[4];
    const float* fc_w     = (const float*)d_in[5];
    const float* fc_b     = (const float*)d_in[6];
    const float* mlp_w    = (const float*)d_in[7];
    const float* mlp_b    = (const float*)d_in[8];
    const int*   routit_p = (const int*)d_in[9];

    float* out = (float*)d_out;
    float* out_logp = out;                       // [NN, 16]
    float* out_h = out + (size_t)NN * NCLASS;    // [NN, 256]

    float* h_buf;
    float* xn_buf;
    cudaGetSymbolAddress((void**)&h_buf, g_h);
    cudaGetSymbolAddress((void**)&xn_buf, g_xn);
    (void)h_buf; (void)xn_buf; (void)in_sizes; (void)n_in; (void)out_size;

    // 1. PCA projection + relu -> g_h
    dim3 ggrid((NN + BM - 1) / BM, DREP / BN);
    pca_gemm_kernel<<<ggrid, 256>>>(x, pca_w, pca_b, h_buf);

    // Layer 0
    prep0_kernel<<<NN + 1, 256>>>(fc_w, fc_b);
    routing_kernel<<<NN, 256>>>(nbrs, rawp, routit_p, h_buf, 1);

    // Layer 1
    prep_norm_kernel<<<NN + 1, 256>>>();
    routing_kernel<<<NN, 256>>>(nbrs, rawp, routit_p, h_buf, 1);

    // Layer 2 (final: no relu, write embedding straight into output)
    prep_norm_kernel<<<NN + 1, 256>>>();
    routing_kernel<<<NN, 256>>>(nbrs, rawp, routit_p, out_h, 0);

    // Classifier head
    int nwarps = NN;
    int nthreads = 256;
    int nblocks = (nwarps * 32 + nthreads - 1) / nthreads;
    mlp_kernel<<<nblocks, nthreads>>>(out_h, mlp_w, mlp_b, out_logp);
}

// round 4
// speedup vs baseline: 1.7885x; 1.7885x over previous
#include <cuda_runtime.h>
#include <cuda_bf16.h>

#define NN 30000
#define MM 16
#define KK 8
#define DDIM 32
#define DREP 256
#define NFEAT 1024
#define NCLASS 16

// Scratch (device globals: allowed, no runtime allocation)
__device__ float g_h[NN * DREP];                 // gemm output
__device__ float g_xn_a[(NN + 1) * DREP];        // normalized table A (+pad)
__device__ float g_xn_b[(NN + 1) * DREP];        // normalized table B (+pad)

// ---------------------------------------------------------------------------
// Packed f32x2 helpers (Blackwell FFMA2: 2x fp32 FMA throughput)
// ---------------------------------------------------------------------------
__device__ __forceinline__ unsigned long long pack_dup(float x) {
    unsigned long long d;
    asm("mov.b64 %0, {%1, %1};" : "=l"(d) : "r"(__float_as_uint(x)));
    return d;
}
__device__ __forceinline__ unsigned long long fma2(unsigned long long a,
                                                   unsigned long long b,
                                                   unsigned long long c) {
    unsigned long long d;
    asm("fma.rn.f32x2 %0, %1, %2, %3;" : "=l"(d) : "l"(a), "l"(b), "l"(c));
    return d;
}

// ---------------------------------------------------------------------------
// PCA GEMM: C = relu(A[NN,1024] @ B[1024,256] + bias), fp32 via FFMA2
// BM=128, BN=64, BK=16, 256 threads, 8x4 micro-tile (4 row-pairs x 4 cols)
// ---------------------------------------------------------------------------
#define BM 128
#define BN 64
#define BK 16

__global__ __launch_bounds__(256) void pca_gemm_kernel(
    const float* __restrict__ A, const float* __restrict__ B,
    const float* __restrict__ bias, float* __restrict__ C)
{
    __shared__ alignas(16) float As[BK][132];   // transposed, padded stride
    __shared__ alignas(16) float Bs[BK][BN];

    int tid = threadIdx.x;
    int rowBase = blockIdx.x * BM;
    int colBase = blockIdx.y * BN;
    int ty = tid >> 4;      // 0..15 -> rows ty*8 .. ty*8+7
    int tx = tid & 15;      // 0..15 -> cols tx*4 .. tx*4+3

    // acc2[ip][j]: packed pair of rows (2*ip, 2*ip+1), col j
    unsigned long long acc2[4][4];
#pragma unroll
    for (int ip = 0; ip < 4; ip++)
#pragma unroll
        for (int j = 0; j < 4; j++) acc2[ip][j] = 0ull;

    for (int k0 = 0; k0 < NFEAT; k0 += BK) {
        // Load A tile (128x16): 512 float4, 2 per thread, store transposed
#pragma unroll
        for (int l = 0; l < 2; l++) {
            int idx = tid + l * 256;
            int r = idx >> 2;
            int c4 = (idx & 3) << 2;
            int row = rowBase + r;
            float4 v = make_float4(0.f, 0.f, 0.f, 0.f);
            if (row < NN)
                v = *(const float4*)(A + (size_t)row * NFEAT + k0 + c4);
            As[c4 + 0][r] = v.x;
            As[c4 + 1][r] = v.y;
            As[c4 + 2][r] = v.z;
            As[c4 + 3][r] = v.w;
        }
        // Load B tile (16x64): 256 float4, 1 per thread
        {
            int r = tid >> 4;
            int c4 = (tid & 15) << 2;
            float4 v = *(const float4*)(B + (size_t)(k0 + r) * DREP + colBase + c4);
            *(float4*)(&Bs[r][c4]) = v;
        }
        __syncthreads();

#pragma unroll
        for (int kk = 0; kk < BK; kk++) {
            // a: 8 rows as 4 packed pairs (adjacent floats in transposed As)
            ulonglong2 aa0 = *(const ulonglong2*)(&As[kk][ty * 8]);
            ulonglong2 aa1 = *(const ulonglong2*)(&As[kk][ty * 8 + 4]);
            float4 bv = *(const float4*)(&Bs[kk][tx * 4]);
            unsigned long long b0 = pack_dup(bv.x);
            unsigned long long b1 = pack_dup(bv.y);
            unsigned long long b2 = pack_dup(bv.z);
            unsigned long long b3 = pack_dup(bv.w);
            acc2[0][0] = fma2(aa0.x, b0, acc2[0][0]);
            acc2[0][1] = fma2(aa0.x, b1, acc2[0][1]);
            acc2[0][2] = fma2(aa0.x, b2, acc2[0][2]);
            acc2[0][3] = fma2(aa0.x, b3, acc2[0][3]);
            acc2[1][0] = fma2(aa0.y, b0, acc2[1][0]);
            acc2[1][1] = fma2(aa0.y, b1, acc2[1][1]);
            acc2[1][2] = fma2(aa0.y, b2, acc2[1][2]);
            acc2[1][3] = fma2(aa0.y, b3, acc2[1][3]);
            acc2[2][0] = fma2(aa1.x, b0, acc2[2][0]);
            acc2[2][1] = fma2(aa1.x, b1, acc2[2][1]);
            acc2[2][2] = fma2(aa1.x, b2, acc2[2][2]);
            acc2[2][3] = fma2(aa1.x, b3, acc2[2][3]);
            acc2[3][0] = fma2(aa1.y, b0, acc2[3][0]);
            acc2[3][1] = fma2(aa1.y, b1, acc2[3][1]);
            acc2[3][2] = fma2(aa1.y, b2, acc2[3][2]);
            acc2[3][3] = fma2(aa1.y, b3, acc2[3][3]);
        }
        __syncthreads();
    }

    float4 bb = *(const float4*)(bias + colBase + tx * 4);
#pragma unroll
    for (int ip = 0; ip < 4; ip++) {
        float2 c0 = *(float2*)&acc2[ip][0];
        float2 c1 = *(float2*)&acc2[ip][1];
        float2 c2 = *(float2*)&acc2[ip][2];
        float2 c3 = *(float2*)&acc2[ip][3];
        int row0 = rowBase + ty * 8 + 2 * ip;
        if (row0 < NN) {
            float4 o0 = make_float4(fmaxf(c0.x + bb.x, 0.f), fmaxf(c1.x + bb.y, 0.f),
                                    fmaxf(c2.x + bb.z, 0.f), fmaxf(c3.x + bb.w, 0.f));
            *(float4*)(C + (size_t)row0 * DREP + colBase + tx * 4) = o0;
        }
        if (row0 + 1 < NN) {
            float4 o1 = make_float4(fmaxf(c0.y + bb.x, 0.f), fmaxf(c1.y + bb.y, 0.f),
                                    fmaxf(c2.y + bb.z, 0.f), fmaxf(c3.y + bb.w, 0.f));
            *(float4*)(C + (size_t)(row0 + 1) * DREP + colBase + tx * 4) = o1;
        }
    }
}

// ---------------------------------------------------------------------------
// Prep layer 0: per-capsule l2norm -> fc (32x32 per capsule) + relu -> l2norm
// One block per node (plus pad block NN), 256 threads: (k = t>>5, o = t&31)
// ---------------------------------------------------------------------------
__global__ __launch_bounds__(256) void prep0_kernel(
    const float* __restrict__ fc_w, const float* __restrict__ fc_b)
{
    int n = blockIdx.x;
    int t = threadIdx.x;
    int k = t >> 5;
    int o = t & 31;
    if (n == NN) { g_xn_a[(size_t)NN * DREP + t] = 0.f; return; }

    __shared__ float sx[DREP];
    float xv = g_h[(size_t)n * DREP + t];
    float ss = xv * xv;
#pragma unroll
    for (int off = 16; off >= 1; off >>= 1)
        ss += __shfl_xor_sync(0xffffffffu, ss, off);
    float xn = xv / fmaxf(sqrtf(ss), 1e-12f);
    sx[t] = xn;
    __syncthreads();

    float y = fc_b[k * DDIM + o];
    const float* w = fc_w + (size_t)(k * DDIM + o) * DDIM;
    const float* xk = &sx[k * DDIM];
#pragma unroll
    for (int i = 0; i < DDIM; i++)
        y = fmaf(xk[i], w[i], y);
    y = fmaxf(y, 0.f);

    float ss2 = y * y;
#pragma unroll
    for (int off = 16; off >= 1; off >>= 1)
        ss2 += __shfl_xor_sync(0xffffffffu, ss2, off);
    g_xn_a[(size_t)n * DREP + t] = y / fmaxf(sqrtf(ss2), 1e-12f);
}

// ---------------------------------------------------------------------------
// Routing: one block per node, 256 threads: (k = warp = t>>5, dd = lane)
// z[m] in registers. Multi-reduce: after 4 exchange steps + bfly16, each
// lane holds p[m = lane&15]; single exp; softmax denominators via smem.
// mode 0: intermediate layer -> relu + per-capsule l2norm -> dst table (grid NN+1, pad)
// mode 1: final layer -> write h to out_h and fused MLP + log_softmax (grid NN)
// ---------------------------------------------------------------------------
__global__ __launch_bounds__(256) void routing_kernel(
    const int* __restrict__ nbrs, const float* __restrict__ raw_param,
    const int* __restrict__ routit_p,
    const float* __restrict__ src_xn, float* __restrict__ dst,
    int mode,
    const float* __restrict__ mlp_w, const float* __restrict__ mlp_b,
    float* __restrict__ out_logp)
{
    int n = blockIdx.x;
    int t = threadIdx.x;
    int k = t >> 5;
    int lane = t & 31;

    if (mode == 0 && n == NN) {      // pad row of destination table
        dst[(size_t)NN * DREP + t] = 0.f;
        return;
    }

    __shared__ int snbr[MM];
    __shared__ float se[KK * MM];    // e matrix [k][m]
    __shared__ float s1s[KK];        // param / s1[k]
    __shared__ float s2s[MM];        // (1-param) / s2[m]
    __shared__ float su[DREP];       // final h (mode 1)
    __shared__ float slog[NCLASS];

    if (t < MM) snbr[t] = nbrs[(size_t)n * MM + t];
    __syncthreads();

    float z[MM];
#pragma unroll
    for (int m = 0; m < MM; m++) {
        int nb = snbr[m];
        z[m] = src_xn[(size_t)nb * DREP + t];
    }
    float u_acc = src_xn[(size_t)n * DREP + t];   // u_before init (normalized)
    float u_n = u_acc;

    float param = 1.f / (1.f + __expf(-raw_param[0]));
    float q = 1.f - param;
    int nit = *routit_p;

    for (int it = 0; it < nit; it++) {
        float pm;
        if (it == 0) {
            pm = 0.f;
        } else {
            float v[MM];
#pragma unroll
            for (int m = 0; m < MM; m++) v[m] = z[m] * u_n;
            // multi-reduce: 16 sums over 32 lanes -> lane holds m = lane&15
            {
                bool hb = lane & 1;
#pragma unroll
                for (int j = 0; j < 8; j++) {
                    float keep = hb ? v[2 * j + 1] : v[2 * j];
                    float send = hb ? v[2 * j] : v[2 * j + 1];
                    v[j] = keep + __shfl_xor_sync(0xffffffffu, send, 1);
                }
            }
            {
                bool hb = (lane >> 1) & 1;
#pragma unroll
                for (int j = 0; j < 4; j++) {
                    float keep = hb ? v[2 * j + 1] : v[2 * j];
                    float send = hb ? v[2 * j] : v[2 * j + 1];
                    v[j] = keep + __shfl_xor_sync(0xffffffffu, send, 2);
                }
            }
            {
                bool hb = (lane >> 2) & 1;
#pragma unroll
                for (int j = 0; j < 2; j++) {
                    float keep = hb ? v[2 * j + 1] : v[2 * j];
                    float send = hb ? v[2 * j] : v[2 * j + 1];
                    v[j] = keep + __shfl_xor_sync(0xffffffffu, send, 4);
                }
            }
            {
                bool hb = (lane >> 3) & 1;
                float keep = hb ? v[1] : v[0];
                float send = hb ? v[0] : v[1];
                v[0] = keep + __shfl_xor_sync(0xffffffffu, send, 8);
            }
            pm = v[0] + __shfl_xor_sync(0xffffffffu, v[0], 16);
        }
        float e = __expf(pm);          // |pm| <= 1, no max shift needed

        if (lane < MM) se[k * MM + lane] = e;
        __syncthreads();
        if (t < KK) {
            float s = 0.f;
#pragma unroll
            for (int m = 0; m < MM; m++) s += se[t * MM + m];
            s1s[t] = __fdividef(param, s);
        } else if (t < KK + MM) {
            int m = t - KK;
            float s = 0.f;
#pragma unroll
            for (int kk = 0; kk < KK; kk++) s += se[kk * MM + m];
            s2s[m] = __fdividef(q, s);
        }
        __syncthreads();

        float w = e * (s1s[k] + s2s[lane & 15]);
        float unew = u_acc;
#pragma unroll
        for (int m = 0; m < MM; m++)
            unew = fmaf(z[m], __shfl_sync(0xffffffffu, w, m), unew);
        u_acc = unew;

        if (it < nit - 1) {
            float ss = u_acc * u_acc;
#pragma unroll
            for (int off = 16; off >= 1; off >>= 1)
                ss += __shfl_xor_sync(0xffffffffu, ss, off);
            u_n = u_acc / fmaxf(sqrtf(ss), 1e-12f);
        }
        __syncthreads();   // protect se/s1s/s2s reuse across iterations
    }

    if (mode == 0) {
        // relu then per-capsule l2norm -> next layer's normalized table
        float v = fmaxf(u_acc, 0.f);
        float ss = v * v;
#pragma unroll
        for (int off = 16; off >= 1; off >>= 1)
            ss += __shfl_xor_sync(0xffffffffu, ss, off);
        dst[(size_t)n * DREP + t] = v / fmaxf(sqrtf(ss), 1e-12f);
    } else {
        // final layer: write embedding + fused MLP + log_softmax
        dst[(size_t)n * DREP + t] = u_acc;
        su[t] = u_acc;
        __syncthreads();
        // warp k computes classes 2k, 2k+1
#pragma unroll
        for (int cc = 0; cc < 2; cc++) {
            int c = k * 2 + cc;
            float acc = 0.f;
#pragma unroll
            for (int j = 0; j < 8; j++)
                acc = fmaf(su[lane + 32 * j],
                           __ldg(&mlp_w[(size_t)c * DREP + lane + 32 * j]), acc);
#pragma unroll
            for (int off = 16; off >= 1; off >>= 1)
                acc += __shfl_xor_sync(0xffffffffu, acc, off);
            if (lane == 0) slog[c] = acc + __ldg(&mlp_b[c]);
        }
        __syncthreads();
        if (t < 32) {
            float x = slog[t & 15];
            float mx = x;
#pragma unroll
            for (int off = 8; off >= 1; off >>= 1)
                mx = fmaxf(mx, __shfl_xor_sync(0xffffffffu, mx, off));
            float ex = __expf(x - mx);
            float s = ex;
#pragma unroll
            for (int off = 8; off >= 1; off >>= 1)
                s += __shfl_xor_sync(0xffffffffu, s, off);
            if (t < NCLASS)
                out_logp[(size_t)n * NCLASS + t] = x - mx - __logf(s);
        }
    }
}

// ---------------------------------------------------------------------------
// Launch
// ---------------------------------------------------------------------------
extern "C" void kernel_launch(void* const* d_in, const int* in_sizes, int n_in,
                              void* d_out, int out_size)
{
    const float* x        = (const float*)d_in[0];
    const int*   nbrs     = (const int*)d_in[1];
    const float* pca_w    = (const float*)d_in[2];
    const float* pca_b    = (const float*)d_in[3];
    const float* rawp     = (const float*)d_in[4];
    const float* fc_w     = (const float*)d_in[5];
    const float* fc_b     = (const float*)d_in[6];
    const float* mlp_w    = (const float*)d_in[7];
    const float* mlp_b    = (const float*)d_in[8];
    const int*   routit_p = (const int*)d_in[9];

    float* out = (float*)d_out;
    float* out_logp = out;                       // [NN, 16]
    float* out_h = out + (size_t)NN * NCLASS;    // [NN, 256]

    float *h_buf, *xa, *xb;
    cudaGetSymbolAddress((void**)&h_buf, g_h);
    cudaGetSymbolAddress((void**)&xa, g_xn_a);
    cudaGetSymbolAddress((void**)&xb, g_xn_b);
    (void)in_sizes; (void)n_in; (void)out_size;

    // 1. PCA projection + relu -> g_h
    dim3 ggrid((NN + BM - 1) / BM, DREP / BN);
    pca_gemm_kernel<<<ggrid, 256>>>(x, pca_w, pca_b, h_buf);

    // 2. Layer-0 prep: capsule norm + fc + relu + norm -> xa (+ pad)
    prep0_kernel<<<NN + 1, 256>>>(fc_w, fc_b);

    // 3. Routing layers (norm fused into epilogue, double-buffered)
    routing_kernel<<<NN + 1, 256>>>(nbrs, rawp, routit_p, xa, xb, 0,
                                    mlp_w, mlp_b, out_logp);
    routing_kernel<<<NN + 1, 256>>>(nbrs, rawp, routit_p, xb, xa, 0,
                                    mlp_w, mlp_b, out_logp);
    // 4. Final layer: embedding + fused MLP head
    routing_kernel<<<NN, 256>>>(nbrs, rawp, routit_p, xa, out_h, 1,
                                mlp_w, mlp_b, out_logp);
}

// round 5
// speedup vs baseline: 1.8051x; 1.0093x over previous
#include <cuda_runtime.h>
#include <cuda_bf16.h>

#define NN 30000
#define MM 16
#define KK 8
#define DDIM 32
#define DREP 256
#define NFEAT 1024
#define NCLASS 16

// Scratch (device globals: allowed, no runtime allocation)
__device__ float g_h[NN * DREP];                 // gemm output
__device__ float g_xn_a[(NN + 1) * DREP];        // normalized table A (+pad)
__device__ float g_xn_b[(NN + 1) * DREP];        // normalized table B (+pad)

// ---------------------------------------------------------------------------
// Packed f32x2 helpers (Blackwell FFMA2: 2x fp32 FMA throughput)
// ---------------------------------------------------------------------------
__device__ __forceinline__ unsigned long long pack_dup(float x) {
    unsigned long long d;
    asm("mov.b64 %0, {%1, %1};" : "=l"(d) : "r"(__float_as_uint(x)));
    return d;
}
__device__ __forceinline__ unsigned long long fma2(unsigned long long a,
                                                   unsigned long long b,
                                                   unsigned long long c) {
    unsigned long long d;
    asm("fma.rn.f32x2 %0, %1, %2, %3;" : "=l"(d) : "l"(a), "l"(b), "l"(c));
    return d;
}

// ---------------------------------------------------------------------------
// PCA GEMM: C = relu(A[NN,1024] @ B[1024,256] + bias), fp32 via FFMA2
// BM=128, BN=128, BK=16, 256 threads, 8x8 micro-tile (4 row-pairs x 8 cols).
// Double-buffered smem with register prefetch; one barrier per k-tile.
// B columns split (tx*4, 64+tx*4) to avoid 4-way LDS bank conflicts.
// ---------------------------------------------------------------------------
#define GBM 128
#define GBN 128
#define GBK 16
#define GNT (NFEAT / GBK)   // 64 k-tiles

__global__ __launch_bounds__(256) void pca_gemm_kernel(
    const float* __restrict__ A, const float* __restrict__ B,
    const float* __restrict__ bias, float* __restrict__ C)
{
    __shared__ alignas(16) float As[2][GBK][132];   // transposed, padded
    __shared__ alignas(16) float Bs[2][GBK][GBN];

    const int tid = threadIdx.x;
    const int rowBase = blockIdx.x * GBM;
    const int colBase = blockIdx.y * GBN;
    const int ty = tid >> 4;      // 0..15 -> rows ty*8..ty*8+7
    const int tx = tid & 15;      // 0..15 -> cols tx*4..+3 and 64+tx*4..+3

    // A-tile load mapping: 128x16 = 512 float4, 2 per thread
    const int ar = tid >> 2;            // 0..63 (+64 for second)
    const int ac = (tid & 3) << 2;
    // B-tile load mapping: 16x128 = 512 float4, 2 per thread
    const int br = tid >> 5;            // 0..7 (+8 for second)
    const int bc = (tid & 31) << 2;

    unsigned long long acc2[4][8];
#pragma unroll
    for (int i = 0; i < 4; i++)
#pragma unroll
        for (int j = 0; j < 8; j++) acc2[i][j] = 0ull;

    float4 pa0, pa1, pb0, pb1;

    // --- prefetch tile 0 ---
    {
        int r0 = rowBase + ar, r1 = rowBase + ar + 64;
        const float* ab = A + ac;
        pa0 = (r0 < NN) ? *(const float4*)(ab + (size_t)r0 * NFEAT)
                        : make_float4(0.f, 0.f, 0.f, 0.f);
        pa1 = (r1 < NN) ? *(const float4*)(ab + (size_t)r1 * NFEAT)
                        : make_float4(0.f, 0.f, 0.f, 0.f);
        const float* bb = B + colBase + bc;
        pb0 = *(const float4*)(bb + (size_t)br * DREP);
        pb1 = *(const float4*)(bb + (size_t)(br + 8) * DREP);
    }
    // store tile 0
    {
        As[0][ac + 0][ar] = pa0.x; As[0][ac + 1][ar] = pa0.y;
        As[0][ac + 2][ar] = pa0.z; As[0][ac + 3][ar] = pa0.w;
        As[0][ac + 0][ar + 64] = pa1.x; As[0][ac + 1][ar + 64] = pa1.y;
        As[0][ac + 2][ar + 64] = pa1.z; As[0][ac + 3][ar + 64] = pa1.w;
        *(float4*)&Bs[0][br][bc] = pb0;
        *(float4*)&Bs[0][br + 8][bc] = pb1;
    }
    __syncthreads();

    for (int t = 0; t < GNT; t++) {
        const int buf = t & 1;
        if (t + 1 < GNT) {
            int koff = (t + 1) * GBK;
            int r0 = rowBase + ar, r1 = rowBase + ar + 64;
            const float* ab = A + koff + ac;
            pa0 = (r0 < NN) ? *(const float4*)(ab + (size_t)r0 * NFEAT)
                            : make_float4(0.f, 0.f, 0.f, 0.f);
            pa1 = (r1 < NN) ? *(const float4*)(ab + (size_t)r1 * NFEAT)
                            : make_float4(0.f, 0.f, 0.f, 0.f);
            const float* bb = B + (size_t)koff * DREP + colBase + bc;
            pb0 = *(const float4*)(bb + (size_t)br * DREP);
            pb1 = *(const float4*)(bb + (size_t)(br + 8) * DREP);
        }

#pragma unroll
        for (int kk = 0; kk < GBK; kk++) {
            ulonglong2 aa0 = *(const ulonglong2*)&As[buf][kk][ty * 8];
            ulonglong2 aa1 = *(const ulonglong2*)&As[buf][kk][ty * 8 + 4];
            float4 b0 = *(const float4*)&Bs[buf][kk][tx * 4];
            float4 b1 = *(const float4*)&Bs[buf][kk][64 + tx * 4];
            unsigned long long av[4] = {aa0.x, aa0.y, aa1.x, aa1.y};
            unsigned long long bd[8] = {
                pack_dup(b0.x), pack_dup(b0.y), pack_dup(b0.z), pack_dup(b0.w),
                pack_dup(b1.x), pack_dup(b1.y), pack_dup(b1.z), pack_dup(b1.w)};
#pragma unroll
            for (int i = 0; i < 4; i++)
#pragma unroll
                for (int j = 0; j < 8; j++)
                    acc2[i][j] = fma2(av[i], bd[j], acc2[i][j]);
        }

        if (t + 1 < GNT) {
            int nb = (t + 1) & 1;
            As[nb][ac + 0][ar] = pa0.x; As[nb][ac + 1][ar] = pa0.y;
            As[nb][ac + 2][ar] = pa0.z; As[nb][ac + 3][ar] = pa0.w;
            As[nb][ac + 0][ar + 64] = pa1.x; As[nb][ac + 1][ar + 64] = pa1.y;
            As[nb][ac + 2][ar + 64] = pa1.z; As[nb][ac + 3][ar + 64] = pa1.w;
            *(float4*)&Bs[nb][br][bc] = pb0;
            *(float4*)&Bs[nb][br + 8][bc] = pb1;
            __syncthreads();
        }
    }

    float4 bi0 = *(const float4*)(bias + colBase + tx * 4);
    float4 bi1 = *(const float4*)(bias + colBase + 64 + tx * 4);
#pragma unroll
    for (int ip = 0; ip < 4; ip++) {
        int row0 = rowBase + ty * 8 + 2 * ip;
        float2 c[8];
#pragma unroll
        for (int j = 0; j < 8; j++) c[j] = *(float2*)&acc2[ip][j];
        if (row0 < NN) {
            float4 o0 = make_float4(fmaxf(c[0].x + bi0.x, 0.f), fmaxf(c[1].x + bi0.y, 0.f),
                                    fmaxf(c[2].x + bi0.z, 0.f), fmaxf(c[3].x + bi0.w, 0.f));
            float4 o1 = make_float4(fmaxf(c[4].x + bi1.x, 0.f), fmaxf(c[5].x + bi1.y, 0.f),
                                    fmaxf(c[6].x + bi1.z, 0.f), fmaxf(c[7].x + bi1.w, 0.f));
            *(float4*)(C + (size_t)row0 * DREP + colBase + tx * 4) = o0;
            *(float4*)(C + (size_t)row0 * DREP + colBase + 64 + tx * 4) = o1;
        }
        if (row0 + 1 < NN) {
            float4 o0 = make_float4(fmaxf(c[0].y + bi0.x, 0.f), fmaxf(c[1].y + bi0.y, 0.f),
                                    fmaxf(c[2].y + bi0.z, 0.f), fmaxf(c[3].y + bi0.w, 0.f));
            float4 o1 = make_float4(fmaxf(c[4].y + bi1.x, 0.f), fmaxf(c[5].y + bi1.y, 0.f),
                                    fmaxf(c[6].y + bi1.z, 0.f), fmaxf(c[7].y + bi1.w, 0.f));
            *(float4*)(C + (size_t)(row0 + 1) * DREP + colBase + tx * 4) = o0;
            *(float4*)(C + (size_t)(row0 + 1) * DREP + colBase + 64 + tx * 4) = o1;
        }
    }
}

// ---------------------------------------------------------------------------
// Prep layer 0: per-capsule l2norm -> fc (32x32 per capsule) + relu -> l2norm
// ---------------------------------------------------------------------------
__global__ __launch_bounds__(256) void prep0_kernel(
    const float* __restrict__ fc_w, const float* __restrict__ fc_b)
{
    int n = blockIdx.x;
    int t = threadIdx.x;
    int k = t >> 5;
    int o = t & 31;
    if (n == NN) { g_xn_a[(size_t)NN * DREP + t] = 0.f; return; }

    __shared__ float sx[DREP];
    float xv = g_h[(size_t)n * DREP + t];
    float ss = xv * xv;
#pragma unroll
    for (int off = 16; off >= 1; off >>= 1)
        ss += __shfl_xor_sync(0xffffffffu, ss, off);
    float xn = xv / fmaxf(sqrtf(ss), 1e-12f);
    sx[t] = xn;
    __syncthreads();

    float y = fc_b[k * DDIM + o];
    const float* w = fc_w + (size_t)(k * DDIM + o) * DDIM;
    const float* xk = &sx[k * DDIM];
#pragma unroll
    for (int i = 0; i < DDIM; i++)
        y = fmaf(xk[i], w[i], y);
    y = fmaxf(y, 0.f);

    float ss2 = y * y;
#pragma unroll
    for (int off = 16; off >= 1; off >>= 1)
        ss2 += __shfl_xor_sync(0xffffffffu, ss2, off);
    g_xn_a[(size_t)n * DREP + t] = y / fmaxf(sqrtf(ss2), 1e-12f);
}

// ---------------------------------------------------------------------------
// Routing: one block per node, 256 threads: (k = warp = t>>5, dd = lane)
// z[m] in registers; multi-reduce leaves p[m=lane&15] per lane; single exp.
// se double-buffered -> ONE barrier per iteration; softmax denominators
// computed redundantly per-thread from smem (broadcast LDS, no divergence).
// mode 0: relu + per-capsule l2norm -> dst table (grid NN+1 incl pad)
// mode 1: final -> h to dst and fused MLP + log_softmax (grid NN)
// ---------------------------------------------------------------------------
__global__ __launch_bounds__(256) void routing_kernel(
    const int* __restrict__ nbrs, const float* __restrict__ raw_param,
    const int* __restrict__ routit_p,
    const float* __restrict__ src_xn, float* __restrict__ dst,
    int mode,
    const float* __restrict__ mlp_w, const float* __restrict__ mlp_b,
    float* __restrict__ out_logp)
{
    int n = blockIdx.x;
    int t = threadIdx.x;
    int k = t >> 5;
    int lane = t & 31;
    int mi = lane & 15;

    if (mode == 0 && n == NN) {      // pad row of destination table
        dst[(size_t)NN * DREP + t] = 0.f;
        return;
    }

    __shared__ int snbr[MM];
    __shared__ float se[2][KK * MM];    // e matrix [k][m], double-buffered
    __shared__ float su[DREP];          // final h (mode 1)
    __shared__ float slog[NCLASS];

    if (t < MM) snbr[t] = nbrs[(size_t)n * MM + t];
    __syncthreads();

    float z[MM];
#pragma unroll
    for (int m = 0; m < MM; m++) {
        int nb = snbr[m];
        z[m] = __ldg(&src_xn[(size_t)nb * DREP + t]);
    }
    float u_acc = __ldg(&src_xn[(size_t)n * DREP + t]);
    float u_n = u_acc;

    float param = 1.f / (1.f + __expf(-raw_param[0]));
    float q = 1.f - param;
    int nit = *routit_p;

    for (int it = 0; it < nit; it++) {
        int buf = it & 1;
        float pm;
        if (it == 0) {
            pm = 0.f;
        } else {
            float v[MM];
#pragma unroll
            for (int m = 0; m < MM; m++) v[m] = z[m] * u_n;
            // multi-reduce: 16 dot-sums over 32 lanes -> lane holds m=lane&15
            {
                bool hb = lane & 1;
#pragma unroll
                for (int j = 0; j < 8; j++) {
                    float keep = hb ? v[2 * j + 1] : v[2 * j];
                    float send = hb ? v[2 * j] : v[2 * j + 1];
                    v[j] = keep + __shfl_xor_sync(0xffffffffu, send, 1);
                }
            }
            {
                bool hb = (lane >> 1) & 1;
#pragma unroll
                for (int j = 0; j < 4; j++) {
                    float keep = hb ? v[2 * j + 1] : v[2 * j];
                    float send = hb ? v[2 * j] : v[2 * j + 1];
                    v[j] = keep + __shfl_xor_sync(0xffffffffu, send, 2);
                }
            }
            {
                bool hb = (lane >> 2) & 1;
#pragma unroll
                for (int j = 0; j < 2; j++) {
                    float keep = hb ? v[2 * j + 1] : v[2 * j];
                    float send = hb ? v[2 * j] : v[2 * j + 1];
                    v[j] = keep + __shfl_xor_sync(0xffffffffu, send, 4);
                }
            }
            {
                bool hb = (lane >> 3) & 1;
                float keep = hb ? v[1] : v[0];
                float send = hb ? v[0] : v[1];
                v[0] = keep + __shfl_xor_sync(0xffffffffu, send, 8);
            }
            pm = v[0] + __shfl_xor_sync(0xffffffffu, v[0], 16);
        }
        float e = __expf(pm);          // |pm| <= 1, no max shift needed

        if (lane < MM) se[buf][k * MM + lane] = e;
        __syncthreads();

        // per-thread redundant softmax denominators (broadcast LDS)
        float s1 = 0.f;
#pragma unroll
        for (int m = 0; m < MM; m++) s1 += se[buf][k * MM + m];
        float s2 = 0.f;
#pragma unroll
        for (int kk = 0; kk < KK; kk++) s2 += se[buf][kk * MM + mi];

        float w = se[buf][k * MM + mi] *
                  (__fdividef(param, s1) + __fdividef(q, s2));
        float unew = u_acc;
#pragma unroll
        for (int m = 0; m < MM; m++)
            unew = fmaf(z[m], __shfl_sync(0xffffffffu, w, m), unew);
        u_acc = unew;

        if (it < nit - 1) {
            float ss = u_acc * u_acc;
#pragma unroll
            for (int off = 16; off >= 1; off >>= 1)
                ss += __shfl_xor_sync(0xffffffffu, ss, off);
            u_n = u_acc / fmaxf(sqrtf(ss), 1e-12f);
        }
        // no trailing barrier: se is double-buffered, next write targets buf^1
    }

    if (mode == 0) {
        float v = fmaxf(u_acc, 0.f);
        float ss = v * v;
#pragma unroll
        for (int off = 16; off >= 1; off >>= 1)
            ss += __shfl_xor_sync(0xffffffffu, ss, off);
        dst[(size_t)n * DREP + t] = v / fmaxf(sqrtf(ss), 1e-12f);
    } else {
        dst[(size_t)n * DREP + t] = u_acc;
        su[t] = u_acc;
        __syncthreads();
#pragma unroll
        for (int cc = 0; cc < 2; cc++) {
            int c = k * 2 + cc;
            float acc = 0.f;
#pragma unroll
            for (int j = 0; j < 8; j++)
                acc = fmaf(su[lane + 32 * j],
                           __ldg(&mlp_w[(size_t)c * DREP + lane + 32 * j]), acc);
#pragma unroll
            for (int off = 16; off >= 1; off >>= 1)
                acc += __shfl_xor_sync(0xffffffffu, acc, off);
            if (lane == 0) slog[c] = acc + __ldg(&mlp_b[c]);
        }
        __syncthreads();
        if (t < 32) {
            float x = slog[t & 15];
            float mx = x;
#pragma unroll
            for (int off = 8; off >= 1; off >>= 1)
                mx = fmaxf(mx, __shfl_xor_sync(0xffffffffu, mx, off));
            float ex = __expf(x - mx);
            float s = ex;
#pragma unroll
            for (int off = 8; off >= 1; off >>= 1)
                s += __shfl_xor_sync(0xffffffffu, s, off);
            if (t < NCLASS)
                out_logp[(size_t)n * NCLASS + t] = x - mx - __logf(s);
        }
    }
}

// ---------------------------------------------------------------------------
// Launch
// ---------------------------------------------------------------------------
extern "C" void kernel_launch(void* const* d_in, const int* in_sizes, int n_in,
                              void* d_out, int out_size)
{
    const float* x        = (const float*)d_in[0];
    const int*   nbrs     = (const int*)d_in[1];
    const float* pca_w    = (const float*)d_in[2];
    const float* pca_b    = (const float*)d_in[3];
    const float* rawp     = (const float*)d_in[4];
    const float* fc_w     = (const float*)d_in[5];
    const float* fc_b     = (const float*)d_in[6];
    const float* mlp_w    = (const float*)d_in[7];
    const float* mlp_b    = (const float*)d_in[8];
    const int*   routit_p = (const int*)d_in[9];

    float* out = (float*)d_out;
    float* out_logp = out;                       // [NN, 16]
    float* out_h = out + (size_t)NN * NCLASS;    // [NN, 256]

    float *h_buf, *xa, *xb;
    cudaGetSymbolAddress((void**)&h_buf, g_h);
    cudaGetSymbolAddress((void**)&xa, g_xn_a);
    cudaGetSymbolAddress((void**)&xb, g_xn_b);
    (void)in_sizes; (void)n_in; (void)out_size;

    // 1. PCA projection + relu -> g_h
    dim3 ggrid((NN + GBM - 1) / GBM, DREP / GBN);
    pca_gemm_kernel<<<ggrid, 256>>>(x, pca_w, pca_b, h_buf);

    // 2. Layer-0 prep: capsule norm + fc + relu + norm -> xa (+ pad)
    prep0_kernel<<<NN + 1, 256>>>(fc_w, fc_b);

    // 3. Routing layers (norm fused into epilogue, double-buffered tables)
    routing_kernel<<<NN + 1, 256>>>(nbrs, rawp, routit_p, xa, xb, 0,
                                    mlp_w, mlp_b, out_logp);
    routing_kernel<<<NN + 1, 256>>>(nbrs, rawp, routit_p, xb, xa, 0,
                                    mlp_w, mlp_b, out_logp);
    // 4. Final layer: embedding + fused MLP head
    routing_kernel<<<NN, 256>>>(nbrs, rawp, routit_p, xa, out_h, 1,
                                mlp_w, mlp_b, out_logp);
}

// round 8
// speedup vs baseline: 2.7685x; 1.5337x over previous
#include <cuda_runtime.h>
#include <cuda_bf16.h>

#define NN 30000
#define MM 16
#define KK 8
#define DDIM 32
#define DREP 256
#define NFEAT 1024
#define NCLASS 16

// Scratch (device globals: allowed, no runtime allocation)
__device__ float g_h[NN * DREP];                 // gemm output
__device__ float g_xn_a[(NN + 1) * DREP];        // normalized table A (+pad)
__device__ float g_xn_b[(NN + 1) * DREP];        // normalized table B (+pad)
__device__ float g_fcwT[KK * DDIM * DDIM];       // fc_w transposed [k][i][o]

// ---------------------------------------------------------------------------
// Packed f32x2 helpers (Blackwell FFMA2: 2x fp32 FMA throughput)
// ---------------------------------------------------------------------------
__device__ __forceinline__ unsigned long long pack_dup(float x) {
    unsigned long long d;
    asm("mov.b64 %0, {%1, %1};" : "=l"(d) : "r"(__float_as_uint(x)));
    return d;
}
__device__ __forceinline__ unsigned long long fma2(unsigned long long a,
                                                   unsigned long long b,
                                                   unsigned long long c) {
    unsigned long long d;
    asm("fma.rn.f32x2 %0, %1, %2, %3;" : "=l"(d) : "l"(a), "l"(b), "l"(c));
    return d;
}

// ---------------------------------------------------------------------------
// PCA GEMM: C = relu(A[NN,1024] @ B[1024,256] + bias), fp32 via FFMA2
// BM=128, BN=128, BK=16, 256 threads, 8x8 micro-tile; double-buffered smem.
// ---------------------------------------------------------------------------
#define GBM 128
#define GBN 128
#define GBK 16
#define GNT (NFEAT / GBK)   // 64 k-tiles

__global__ __launch_bounds__(256) void pca_gemm_kernel(
    const float* __restrict__ A, const float* __restrict__ B,
    const float* __restrict__ bias, float* __restrict__ C)
{
    __shared__ alignas(16) float As[2][GBK][132];   // transposed, padded
    __shared__ alignas(16) float Bs[2][GBK][GBN];

    const int tid = threadIdx.x;
    const int rowBase = blockIdx.x * GBM;
    const int colBase = blockIdx.y * GBN;
    const int ty = tid >> 4;      // 0..15 -> rows ty*8..ty*8+7
    const int tx = tid & 15;      // 0..15 -> cols tx*4..+3 and 64+tx*4..+3

    const int ar = tid >> 2;            // 0..63 (+64 for second)
    const int ac = (tid & 3) << 2;
    const int br = tid >> 5;            // 0..7 (+8 for second)
    const int bc = (tid & 31) << 2;

    unsigned long long acc2[4][8];
#pragma unroll
    for (int i = 0; i < 4; i++)
#pragma unroll
        for (int j = 0; j < 8; j++) acc2[i][j] = 0ull;

    float4 pa0, pa1, pb0, pb1;

    {
        int r0 = rowBase + ar, r1 = rowBase + ar + 64;
        const float* ab = A + ac;
        pa0 = (r0 < NN) ? *(const float4*)(ab + (size_t)r0 * NFEAT)
                        : make_float4(0.f, 0.f, 0.f, 0.f);
        pa1 = (r1 < NN) ? *(const float4*)(ab + (size_t)r1 * NFEAT)
                        : make_float4(0.f, 0.f, 0.f, 0.f);
        const float* bb = B + colBase + bc;
        pb0 = *(const float4*)(bb + (size_t)br * DREP);
        pb1 = *(const float4*)(bb + (size_t)(br + 8) * DREP);
    }
    {
        As[0][ac + 0][ar] = pa0.x; As[0][ac + 1][ar] = pa0.y;
        As[0][ac + 2][ar] = pa0.z; As[0][ac + 3][ar] = pa0.w;
        As[0][ac + 0][ar + 64] = pa1.x; As[0][ac + 1][ar + 64] = pa1.y;
        As[0][ac + 2][ar + 64] = pa1.z; As[0][ac + 3][ar + 64] = pa1.w;
        *(float4*)&Bs[0][br][bc] = pb0;
        *(float4*)&Bs[0][br + 8][bc] = pb1;
    }
    __syncthreads();

    for (int t = 0; t < GNT; t++) {
        const int buf = t & 1;
        if (t + 1 < GNT) {
            int koff = (t + 1) * GBK;
            int r0 = rowBase + ar, r1 = rowBase + ar + 64;
            const float* ab = A + koff + ac;
            pa0 = (r0 < NN) ? *(const float4*)(ab + (size_t)r0 * NFEAT)
                            : make_float4(0.f, 0.f, 0.f, 0.f);
            pa1 = (r1 < NN) ? *(const float4*)(ab + (size_t)r1 * NFEAT)
                            : make_float4(0.f, 0.f, 0.f, 0.f);
            const float* bb = B + (size_t)koff * DREP + colBase + bc;
            pb0 = *(const float4*)(bb + (size_t)br * DREP);
            pb1 = *(const float4*)(bb + (size_t)(br + 8) * DREP);
        }

#pragma unroll
        for (int kk = 0; kk < GBK; kk++) {
            ulonglong2 aa0 = *(const ulonglong2*)&As[buf][kk][ty * 8];
            ulonglong2 aa1 = *(const ulonglong2*)&As[buf][kk][ty * 8 + 4];
            float4 b0 = *(const float4*)&Bs[buf][kk][tx * 4];
            float4 b1 = *(const float4*)&Bs[buf][kk][64 + tx * 4];
            unsigned long long av[4] = {aa0.x, aa0.y, aa1.x, aa1.y};
            unsigned long long bd[8] = {
                pack_dup(b0.x), pack_dup(b0.y), pack_dup(b0.z), pack_dup(b0.w),
                pack_dup(b1.x), pack_dup(b1.y), pack_dup(b1.z), pack_dup(b1.w)};
#pragma unroll
            for (int i = 0; i < 4; i++)
#pragma unroll
                for (int j = 0; j < 8; j++)
                    acc2[i][j] = fma2(av[i], bd[j], acc2[i][j]);
        }

        if (t + 1 < GNT) {
            int nb = (t + 1) & 1;
            As[nb][ac + 0][ar] = pa0.x; As[nb][ac + 1][ar] = pa0.y;
            As[nb][ac + 2][ar] = pa0.z; As[nb][ac + 3][ar] = pa0.w;
            As[nb][ac + 0][ar + 64] = pa1.x; As[nb][ac + 1][ar + 64] = pa1.y;
            As[nb][ac + 2][ar + 64] = pa1.z; As[nb][ac + 3][ar + 64] = pa1.w;
            *(float4*)&Bs[nb][br][bc] = pb0;
            *(float4*)&Bs[nb][br + 8][bc] = pb1;
            __syncthreads();
        }
    }

    float4 bi0 = *(const float4*)(bias + colBase + tx * 4);
    float4 bi1 = *(const float4*)(bias + colBase + 64 + tx * 4);
#pragma unroll
    for (int ip = 0; ip < 4; ip++) {
        int row0 = rowBase + ty * 8 + 2 * ip;
        float2 c[8];
#pragma unroll
        for (int j = 0; j < 8; j++) c[j] = *(float2*)&acc2[ip][j];
        if (row0 < NN) {
            float4 o0 = make_float4(fmaxf(c[0].x + bi0.x, 0.f), fmaxf(c[1].x + bi0.y, 0.f),
                                    fmaxf(c[2].x + bi0.z, 0.f), fmaxf(c[3].x + bi0.w, 0.f));
            float4 o1 = make_float4(fmaxf(c[4].x + bi1.x, 0.f), fmaxf(c[5].x + bi1.y, 0.f),
                                    fmaxf(c[6].x + bi1.z, 0.f), fmaxf(c[7].x + bi1.w, 0.f));
            *(float4*)(C + (size_t)row0 * DREP + colBase + tx * 4) = o0;
            *(float4*)(C + (size_t)row0 * DREP + colBase + 64 + tx * 4) = o1;
        }
        if (row0 + 1 < NN) {
            float4 o0 = make_float4(fmaxf(c[0].y + bi0.x, 0.f), fmaxf(c[1].y + bi0.y, 0.f),
                                    fmaxf(c[2].y + bi0.z, 0.f), fmaxf(c[3].y + bi0.w, 0.f));
            float4 o1 = make_float4(fmaxf(c[4].y + bi1.x, 0.f), fmaxf(c[5].y + bi1.y, 0.f),
                                    fmaxf(c[6].y + bi1.z, 0.f), fmaxf(c[7].y + bi1.w, 0.f));
            *(float4*)(C + (size_t)(row0 + 1) * DREP + colBase + tx * 4) = o0;
            *(float4*)(C + (size_t)(row0 + 1) * DREP + colBase + 64 + tx * 4) = o1;
        }
    }
}

// ---------------------------------------------------------------------------
// Transpose fc_w [k][o][i] -> g_fcwT [k][i][o] (one-time, tiny)
// ---------------------------------------------------------------------------
__global__ __launch_bounds__(256) void fcw_transpose_kernel(
    const float* __restrict__ fc_w)
{
    int g = blockIdx.x * 256 + threadIdx.x;   // 0..8191
    int k = g >> 10;
    int r = g & 1023;
    int o = r >> 5;
    int i = r & 31;
    g_fcwT[k * 1024 + i * 32 + o] = fc_w[g];
}

// ---------------------------------------------------------------------------
// Prep layer 0: per-capsule l2norm -> fc (32x32 per capsule, transposed
// weights => coalesced) + relu -> l2norm
// ---------------------------------------------------------------------------
__global__ __launch_bounds__(256) void prep0_kernel(
    const float* __restrict__ fc_b)
{
    int n = blockIdx.x;
    int t = threadIdx.x;
    int k = t >> 5;
    int o = t & 31;
    if (n == NN) { g_xn_a[(size_t)NN * DREP + t] = 0.f; return; }

    __shared__ float sx[DREP];
    float xv = g_h[(size_t)n * DREP + t];
    float ss = xv * xv;
#pragma unroll
    for (int off = 16; off >= 1; off >>= 1)
        ss += __shfl_xor_sync(0xffffffffu, ss, off);
    float xn = xv / fmaxf(sqrtf(ss), 1e-12f);
    sx[t] = xn;
    __syncthreads();

    float y = fc_b[k * DDIM + o];
    const float* wT = g_fcwT + k * DDIM * DDIM + o;   // [i][o], lane=o coalesced
    const float* xk = &sx[k * DDIM];
#pragma unroll
    for (int i = 0; i < DDIM; i++)
        y = fmaf(xk[i], wT[i * DDIM], y);
    y = fmaxf(y, 0.f);

    float ss2 = y * y;
#pragma unroll
    for (int off = 16; off >= 1; off >>= 1)
        ss2 += __shfl_xor_sync(0xffffffffu, ss2, off);
    g_xn_a[(size_t)n * DREP + t] = y / fmaxf(sqrtf(ss2), 1e-12f);
}

// ---------------------------------------------------------------------------
// Routing: one block per node, 256 threads: (k = warp = t>>5, dd = lane)
// Iteration 0 hoisted (uniform softmax weights -> single fma on Σz).
// Multi-reduce leaves p[m=lane&15] per lane; single exp; s1 via 4-shfl
// warp reduce; s2 (cross-warp) via double-buffered smem; one barrier/iter.
// mode 0: relu + per-capsule l2norm -> dst table (grid NN+1 incl pad)
// mode 1: final -> h to dst and fused MLP + log_softmax (grid NN)
// ---------------------------------------------------------------------------
__global__ __launch_bounds__(256) void routing_kernel(
    const int* __restrict__ nbrs, const float* __restrict__ raw_param,
    const int* __restrict__ routit_p,
    const float* __restrict__ src_xn, float* __restrict__ dst,
    int mode,
    const float* __restrict__ mlp_w, const float* __restrict__ mlp_b,
    float* __restrict__ out_logp)
{
    int n = blockIdx.x;
    int t = threadIdx.x;
    int k = t >> 5;
    int lane = t & 31;
    int mi = lane & 15;

    if (mode == 0 && n == NN) {      // pad row of destination table
        dst[(size_t)NN * DREP + t] = 0.f;
        return;
    }

    __shared__ int snbr[MM];
    __shared__ float se[2][KK * MM];    // e matrix [k][m], double-buffered
    __shared__ float su[DREP];          // final h (mode 1)
    __shared__ float slog[NCLASS];

    if (t < MM) snbr[t] = nbrs[(size_t)n * MM + t];
    __syncthreads();

    float z[MM];
#pragma unroll
    for (int m = 0; m < MM; m++) {
        int nb = snbr[m];
        z[m] = __ldg(&src_xn[(size_t)nb * DREP + t]);
    }
    float u_acc = __ldg(&src_xn[(size_t)n * DREP + t]);

    float param = 1.f / (1.f + __expf(-raw_param[0]));
    float q = 1.f - param;
    int nit = *routit_p;

    // --- iteration 0 (p == 0 -> uniform softmaxes: 1/16 and 1/8) ---
    {
        float zsum = 0.f;
#pragma unroll
        for (int m = 0; m < MM; m++) zsum += z[m];
        float w0 = param * (1.f / 16.f) + q * (1.f / 8.f);
        u_acc = fmaf(zsum, w0, u_acc);
    }
    float u_n = u_acc;
    if (nit > 1) {
        float ss = u_acc * u_acc;
#pragma unroll
        for (int off = 16; off >= 1; off >>= 1)
            ss += __shfl_xor_sync(0xffffffffu, ss, off);
        u_n = u_acc / fmaxf(sqrtf(ss), 1e-12f);
    }

    for (int it = 1; it < nit; it++) {
        int buf = it & 1;
        float v[MM];
#pragma unroll
        for (int m = 0; m < MM; m++) v[m] = z[m] * u_n;
        // multi-reduce: 16 dot-sums over 32 lanes -> lane holds m=lane&15
        {
            bool hb = lane & 1;
#pragma unroll
            for (int j = 0; j < 8; j++) {
                float keep = hb ? v[2 * j + 1] : v[2 * j];
                float send = hb ? v[2 * j] : v[2 * j + 1];
                v[j] = keep + __shfl_xor_sync(0xffffffffu, send, 1);
            }
        }
        {
            bool hb = (lane >> 1) & 1;
#pragma unroll
            for (int j = 0; j < 4; j++) {
                float keep = hb ? v[2 * j + 1] : v[2 * j];
                float send = hb ? v[2 * j] : v[2 * j + 1];
                v[j] = keep + __shfl_xor_sync(0xffffffffu, send, 2);
            }
        }
        {
            bool hb = (lane >> 2) & 1;
#pragma unroll
            for (int j = 0; j < 2; j++) {
                float keep = hb ? v[2 * j + 1] : v[2 * j];
                float send = hb ? v[2 * j] : v[2 * j + 1];
                v[j] = keep + __shfl_xor_sync(0xffffffffu, send, 4);
            }
        }
        {
            bool hb = (lane >> 3) & 1;
            float keep = hb ? v[1] : v[0];
            float send = hb ? v[0] : v[1];
            v[0] = keep + __shfl_xor_sync(0xffffffffu, send, 8);
        }
        float pm = v[0] + __shfl_xor_sync(0xffffffffu, v[0], 16);
        float e = __expf(pm);          // |pm| <= 1, no max shift needed

        // s1 = sum over m of e[k][m]: e replicated across half-warps,
        // lanes 0..15 hold m=0..15 -> 4-step shfl reduce within halves
        float s1 = e;
        s1 += __shfl_xor_sync(0xffffffffu, s1, 1);
        s1 += __shfl_xor_sync(0xffffffffu, s1, 2);
        s1 += __shfl_xor_sync(0xffffffffu, s1, 4);
        s1 += __shfl_xor_sync(0xffffffffu, s1, 8);

        if (lane < MM) se[buf][k * MM + lane] = e;
        __syncthreads();

        // s2 = sum over k of e[k][m] (cross-warp, via smem broadcast)
        float s2 = 0.f;
#pragma unroll
        for (int kk = 0; kk < KK; kk++) s2 += se[buf][kk * MM + mi];

        float w = e * (__fdividef(param, s1) + __fdividef(q, s2));
        float unew = u_acc;
#pragma unroll
        for (int m = 0; m < MM; m++)
            unew = fmaf(z[m], __shfl_sync(0xffffffffu, w, m), unew);
        u_acc = unew;

        if (it < nit - 1) {
            float ss = u_acc * u_acc;
#pragma unroll
            for (int off = 16; off >= 1; off >>= 1)
                ss += __shfl_xor_sync(0xffffffffu, ss, off);
            u_n = u_acc / fmaxf(sqrtf(ss), 1e-12f);
        }
        // no trailing barrier: se double-buffered, next write goes to buf^1
    }

    if (mode == 0) {
        float v = fmaxf(u_acc, 0.f);
        float ss = v * v;
#pragma unroll
        for (int off = 16; off >= 1; off >>= 1)
            ss += __shfl_xor_sync(0xffffffffu, ss, off);
        dst[(size_t)n * DREP + t] = v / fmaxf(sqrtf(ss), 1e-12f);
    } else {
        dst[(size_t)n * DREP + t] = u_acc;
        su[t] = u_acc;
        __syncthreads();
#pragma unroll
        for (int cc = 0; cc < 2; cc++) {
            int c = k * 2 + cc;
            float acc = 0.f;
#pragma unroll
            for (int j = 0; j < 8; j++)
                acc = fmaf(su[lane + 32 * j],
                           __ldg(&mlp_w[(size_t)c * DREP + lane + 32 * j]), acc);
#pragma unroll
            for (int off = 16; off >= 1; off >>= 1)
                acc += __shfl_xor_sync(0xffffffffu, acc, off);
            if (lane == 0) slog[c] = acc + __ldg(&mlp_b[c]);
        }
        __syncthreads();
        if (t < 32) {
            float x = slog[t & 15];
            float mx = x;
#pragma unroll
            for (int off = 8; off >= 1; off >>= 1)
                mx = fmaxf(mx, __shfl_xor_sync(0xffffffffu, mx, off));
            float ex = __expf(x - mx);
            float s = ex;
#pragma unroll
            for (int off = 8; off >= 1; off >>= 1)
                s += __shfl_xor_sync(0xffffffffu, s, off);
            if (t < NCLASS)
                out_logp[(size_t)n * NCLASS + t] = x - mx - __logf(s);
        }
    }
}

// ---------------------------------------------------------------------------
// Launch
// ---------------------------------------------------------------------------
extern "C" void kernel_launch(void* const* d_in, const int* in_sizes, int n_in,
                              void* d_out, int out_size)
{
    const float* x        = (const float*)d_in[0];
    const int*   nbrs     = (const int*)d_in[1];
    const float* pca_w    = (const float*)d_in[2];
    const float* pca_b    = (const float*)d_in[3];
    const float* rawp     = (const float*)d_in[4];
    const float* fc_w     = (const float*)d_in[5];
    const float* fc_b     = (const float*)d_in[6];
    const float* mlp_w    = (const float*)d_in[7];
    const float* mlp_b    = (const float*)d_in[8];
    const int*   routit_p = (const int*)d_in[9];

    float* out = (float*)d_out;
    float* out_logp = out;                       // [NN, 16]
    float* out_h = out + (size_t)NN * NCLASS;    // [NN, 256]

    float *h_buf, *xa, *xb;
    cudaGetSymbolAddress((void**)&h_buf, g_h);
    cudaGetSymbolAddress((void**)&xa, g_xn_a);
    cudaGetSymbolAddress((void**)&xb, g_xn_b);
    (void)in_sizes; (void)n_in; (void)out_size;

    // 0. One-time fc weight transpose (coalesces prep0's gather)
    fcw_transpose_kernel<<<KK * DDIM * DDIM / 256, 256>>>(fc_w);

    // 1. PCA projection + relu -> g_h
    dim3 ggrid((NN + GBM - 1) / GBM, DREP / GBN);
    pca_gemm_kernel<<<ggrid, 256>>>(x, pca_w, pca_b, h_buf);

    // 2. Layer-0 prep: capsule norm + fc + relu + norm -> xa (+ pad)
    prep0_kernel<<<NN + 1, 256>>>(fc_b);

    // 3. Routing layers (norm fused into epilogue, double-buffered tables)
    routing_kernel<<<NN + 1, 256>>>(nbrs, rawp, routit_p, xa, xb, 0,
                                    mlp_w, mlp_b, out_logp);
    routing_kernel<<<NN + 1, 256>>>(nbrs, rawp, routit_p, xb, xa, 0,
                                    mlp_w, mlp_b, out_logp);
    // 4. Final layer: embedding + fused MLP head
    routing_kernel<<<NN, 256>>>(nbrs, rawp, routit_p, xa, out_h, 1,
                                mlp_w, mlp_b, out_logp);
}